// round 2
// baseline (speedup 1.0000x reference)
#include <cuda_runtime.h>

// DotProductAttention: B=4, H=8, S=2048, D=16, fp32.
// logits = 10*tanh(QK^T * SCALE); mask (per b,key, int32 0/1) == 1 -> -1e10;
// softmax over keys; output = P @ V.
//
// fp32 CUDA-core flash-style kernel:
//  - one thread per query, D=16 accumulator in registers
//  - K/V tiles (128 keys x 16) staged in shared memory, float4 broadcast reads
//  - fixed softmax max = 10 (tanh bounded): p = exp(t-10) = exp(-20/(e^{2s}+1))
//  - mask is warp-uniform per key -> uniform branch skips ~50% of keys

#define S_LEN   2048
#define D_DIM   16
#define H_NUM   8
#define QT      128      // queries per block (= threads per block)
#define KT      128      // key tile

#define SCALE_F 0.38288785f   // log(400)/log(50)/sqrt(16)
#define CLIP_F  10.0f

__global__ __launch_bounds__(QT)
void attn_fp32_kernel(const float* __restrict__ Q,
                      const float* __restrict__ K,
                      const float* __restrict__ V,
                      const int* __restrict__ mask,   // int32 0/1, [B, S]
                      float* __restrict__ O)
{
    __shared__ float Ks[KT * D_DIM];
    __shared__ float Vs[KT * D_DIM];
    __shared__ int   Ms[KT];

    const int bh = blockIdx.y;            // 0..31  (b*H + h)
    const int b  = bh >> 3;               // H = 8
    const int q  = blockIdx.x * QT + threadIdx.x;

    const float* Qp = Q + ((size_t)bh * S_LEN + q) * D_DIM;
    const float* Kb = K + (size_t)bh * S_LEN * D_DIM;
    const float* Vb = V + (size_t)bh * S_LEN * D_DIM;
    const int*   Mb = mask + (size_t)b * S_LEN;

    // Load this thread's query into registers (16 floats).
    float qr[D_DIM];
#pragma unroll
    for (int i = 0; i < 4; i++) {
        float4 t = reinterpret_cast<const float4*>(Qp)[i];
        qr[4*i+0] = t.x; qr[4*i+1] = t.y; qr[4*i+2] = t.z; qr[4*i+3] = t.w;
    }

    float acc[D_DIM];
#pragma unroll
    for (int d = 0; d < D_DIM; d++) acc[d] = 0.0f;
    float ssum = 0.0f;

    for (int k0 = 0; k0 < S_LEN; k0 += KT) {
        __syncthreads();   // previous-iteration smem reads done
        // Cooperative tile load: KT*D = 2048 floats for K and V each.
#pragma unroll
        for (int i = 0; i < (KT * D_DIM) / (QT * 4); i++) {
            int idx = i * QT + threadIdx.x;
            reinterpret_cast<float4*>(Ks)[idx] =
                reinterpret_cast<const float4*>(Kb + (size_t)k0 * D_DIM)[idx];
            reinterpret_cast<float4*>(Vs)[idx] =
                reinterpret_cast<const float4*>(Vb + (size_t)k0 * D_DIM)[idx];
        }
        if (threadIdx.x < KT)
            Ms[threadIdx.x] = Mb[k0 + threadIdx.x];
        __syncthreads();

#pragma unroll 4
        for (int j = 0; j < KT; j++) {
            const float4* kr = reinterpret_cast<const float4*>(Ks + j * D_DIM);
            float4 ka = kr[0], kb4 = kr[1], kc = kr[2], kd = kr[3];
            // 4-way partial sums for ILP (breaks the 16-deep FFMA chain).
            float p0 = qr[0]  * ka.x  + qr[1]  * ka.y  + qr[2]  * ka.z  + qr[3]  * ka.w;
            float p1 = qr[4]  * kb4.x + qr[5]  * kb4.y + qr[6]  * kb4.z + qr[7]  * kb4.w;
            float p2 = qr[8]  * kc.x  + qr[9]  * kc.y  + qr[10] * kc.z  + qr[11] * kc.w;
            float p3 = qr[12] * kd.x  + qr[13] * kd.y  + qr[14] * kd.z  + qr[15] * kd.w;
            float dot = (p0 + p1) + (p2 + p3);

            if (Ms[j] == 0) {                    // warp-uniform branch
                float s = dot * SCALE_F;
                // t = 10*tanh(s);  p = exp(t - 10) = exp(-20 / (e^{2s} + 1))
                float e  = __expf(2.0f * s);
                float p  = __expf(-2.0f * CLIP_F * __fdividef(1.0f, e + 1.0f));
                ssum += p;
                const float4* vr = reinterpret_cast<const float4*>(Vs + j * D_DIM);
                float4 va = vr[0], vb4 = vr[1], vc = vr[2], vd = vr[3];
                acc[0]  = fmaf(p, va.x,  acc[0]);  acc[1]  = fmaf(p, va.y,  acc[1]);
                acc[2]  = fmaf(p, va.z,  acc[2]);  acc[3]  = fmaf(p, va.w,  acc[3]);
                acc[4]  = fmaf(p, vb4.x, acc[4]);  acc[5]  = fmaf(p, vb4.y, acc[5]);
                acc[6]  = fmaf(p, vb4.z, acc[6]);  acc[7]  = fmaf(p, vb4.w, acc[7]);
                acc[8]  = fmaf(p, vc.x,  acc[8]);  acc[9]  = fmaf(p, vc.y,  acc[9]);
                acc[10] = fmaf(p, vc.z,  acc[10]); acc[11] = fmaf(p, vc.w,  acc[11]);
                acc[12] = fmaf(p, vd.x,  acc[12]); acc[13] = fmaf(p, vd.y,  acc[13]);
                acc[14] = fmaf(p, vd.z,  acc[14]); acc[15] = fmaf(p, vd.w,  acc[15]);
            }
        }
    }

    // Normalize and write out (16 contiguous floats per query).
    float inv = 1.0f / ssum;
    float* Op = O + ((size_t)bh * S_LEN + q) * D_DIM;
#pragma unroll
    for (int i = 0; i < 4; i++) {
        float4 t;
        t.x = acc[4*i+0] * inv; t.y = acc[4*i+1] * inv;
        t.z = acc[4*i+2] * inv; t.w = acc[4*i+3] * inv;
        reinterpret_cast<float4*>(Op)[i] = t;
    }
}

extern "C" void kernel_launch(void* const* d_in, const int* in_sizes, int n_in,
                              void* d_out, int out_size)
{
    const float* Q = (const float*)d_in[0];
    const float* K = (const float*)d_in[1];
    const float* V = (const float*)d_in[2];
    const int* mask = (const int*)d_in[3];
    float* O = (float*)d_out;

    dim3 grid(S_LEN / QT, 4 * H_NUM);   // (16, 32)
    dim3 block(QT);
    attn_fp32_kernel<<<grid, block>>>(Q, K, V, mask, O);
}

// round 3
// speedup vs baseline: 1.8934x; 1.8934x over previous
#include <cuda_runtime.h>

// DotProductAttention: B=4, H=8, S=2048, D=16, fp32.
// logits = 10*tanh(QK^T*SCALE); mask(b,key)==1 -> -1e10; softmax; O = P@V.
//
// R3 design:
//  - Fixed softmax max = 10 (tanh bounded) => p = exp(t-10) = exp(-20/(e^{2s}+1)),
//    which is exactly associative across key chunks: split-K x8 + deterministic reduce.
//  - 2 queries per thread: K/V smem broadcast reads amortized 2x.
//  - Mask packed to a per-warp ballot bitmask kept in registers; masked keys skip
//    ALL work (dot included).
//  - Partials (sum, acc[16]) to __device__ scratch; second kernel reduces+normalizes.

#define S_LEN   2048
#define D_DIM   16
#define H_NUM   8
#define B_NUM   4
#define NQ      65536          // B*H*S total queries
#define QT      128            // threads per block
#define QPB     256            // queries per block (2 per thread)
#define KT      128            // key tile in smem
#define SPLIT   8
#define KCHUNK  (S_LEN / SPLIT)   // 256 keys per block

// C1 = 2*SCALE*log2(e),  C2 = -2*CLIP*log2(e)
#define C1_F  1.1047800f
#define C2_F  (-28.85390082f)

__device__ float g_pacc[(size_t)SPLIT * NQ * D_DIM];  // 33.5 MB
__device__ float g_psum[(size_t)SPLIT * NQ];          //  2.0 MB

__device__ __forceinline__ float ex2f(float x) {
    float r; asm("ex2.approx.ftz.f32 %0, %1;" : "=f"(r) : "f"(x)); return r;
}
__device__ __forceinline__ float rcpf(float x) {
    float r; asm("rcp.approx.ftz.f32 %0, %1;" : "=f"(r) : "f"(x)); return r;
}

__global__ __launch_bounds__(QT)
void attn_partial_kernel(const float* __restrict__ Q,
                         const float* __restrict__ K,
                         const float* __restrict__ V,
                         const int* __restrict__ mask,   // int32 0/1, [B,S]
                         float* __restrict__ O /*unused here*/)
{
    __shared__ float    Ks[KT * D_DIM];
    __shared__ float    Vs[KT * D_DIM];
    __shared__ unsigned MsBits[KT / 32];

    const int bh    = blockIdx.y;      // 0..31
    const int b     = bh >> 3;         // H = 8
    const int split = blockIdx.z;      // 0..7
    const int tid   = threadIdx.x;
    const int qA    = blockIdx.x * QPB + tid;        // within-sequence query idx
    const int qB    = qA + QT;

    const float* Kb = K + (size_t)bh * S_LEN * D_DIM;
    const float* Vb = V + (size_t)bh * S_LEN * D_DIM;
    const int*   Mb = mask + (size_t)b * S_LEN;

    // Load both queries, pre-scaled by C1 so u = exp2(dot) directly.
    float qa[D_DIM], qb[D_DIM];
    {
        const float4* pa = reinterpret_cast<const float4*>(Q + ((size_t)bh * S_LEN + qA) * D_DIM);
        const float4* pb = reinterpret_cast<const float4*>(Q + ((size_t)bh * S_LEN + qB) * D_DIM);
#pragma unroll
        for (int i = 0; i < 4; i++) {
            float4 ta = pa[i], tb = pb[i];
            qa[4*i+0] = ta.x * C1_F; qa[4*i+1] = ta.y * C1_F;
            qa[4*i+2] = ta.z * C1_F; qa[4*i+3] = ta.w * C1_F;
            qb[4*i+0] = tb.x * C1_F; qb[4*i+1] = tb.y * C1_F;
            qb[4*i+2] = tb.z * C1_F; qb[4*i+3] = tb.w * C1_F;
        }
    }

    float accA[D_DIM], accB[D_DIM];
#pragma unroll
    for (int d = 0; d < D_DIM; d++) { accA[d] = 0.0f; accB[d] = 0.0f; }
    float sumA = 0.0f, sumB = 0.0f;

    const int kbeg = split * KCHUNK;
    for (int k0 = kbeg; k0 < kbeg + KCHUNK; k0 += KT) {
        __syncthreads();
        // Cooperative tile load: 128 keys x 16 floats for K and V (4 float4 each/thread).
#pragma unroll
        for (int i = 0; i < (KT * D_DIM) / (QT * 4); i++) {
            int idx = i * QT + tid;
            reinterpret_cast<float4*>(Ks)[idx] =
                reinterpret_cast<const float4*>(Kb + (size_t)k0 * D_DIM)[idx];
            reinterpret_cast<float4*>(Vs)[idx] =
                reinterpret_cast<const float4*>(Vb + (size_t)k0 * D_DIM)[idx];
        }
        // Pack mask tile into 4 ballot words (1 = masked).
        {
            int m = Mb[k0 + tid];
            unsigned bal = __ballot_sync(0xffffffffu, m != 0);
            if ((tid & 31) == 0) MsBits[tid >> 5] = bal;
        }
        __syncthreads();

        unsigned mw0 = MsBits[0], mw1 = MsBits[1], mw2 = MsBits[2], mw3 = MsBits[3];
        unsigned mws[4] = {mw0, mw1, mw2, mw3};

#pragma unroll
        for (int w = 0; w < 4; w++) {
            unsigned bits = mws[w];
#pragma unroll 4
            for (int jj = 0; jj < 32; jj++) {
                if (((bits >> jj) & 1u) == 0u) {       // warp-uniform: unmasked key
                    const int j = w * 32 + jj;
                    const float4* kr = reinterpret_cast<const float4*>(Ks + j * D_DIM);
                    float4 k0v = kr[0], k1v = kr[1], k2v = kr[2], k3v = kr[3];

                    float a0 = qa[0]*k0v.x + qa[1]*k0v.y + qa[2]*k0v.z + qa[3]*k0v.w;
                    float a1 = qa[4]*k1v.x + qa[5]*k1v.y + qa[6]*k1v.z + qa[7]*k1v.w;
                    float a2 = qa[8]*k2v.x + qa[9]*k2v.y + qa[10]*k2v.z + qa[11]*k2v.w;
                    float a3 = qa[12]*k3v.x + qa[13]*k3v.y + qa[14]*k3v.z + qa[15]*k3v.w;
                    float b0 = qb[0]*k0v.x + qb[1]*k0v.y + qb[2]*k0v.z + qb[3]*k0v.w;
                    float b1 = qb[4]*k1v.x + qb[5]*k1v.y + qb[6]*k1v.z + qb[7]*k1v.w;
                    float b2 = qb[8]*k2v.x + qb[9]*k2v.y + qb[10]*k2v.z + qb[11]*k2v.w;
                    float b3 = qb[12]*k3v.x + qb[13]*k3v.y + qb[14]*k3v.z + qb[15]*k3v.w;
                    float dA = (a0 + a1) + (a2 + a3);    // = 2*SCALE*log2e * (q.k)
                    float dB = (b0 + b1) + (b2 + b3);

                    // p = exp2(C2 / (exp2(d) + 1))
                    float uA = ex2f(dA), uB = ex2f(dB);
                    float pA = ex2f(C2_F * rcpf(uA + 1.0f));
                    float pB = ex2f(C2_F * rcpf(uB + 1.0f));
                    sumA += pA; sumB += pB;

                    const float4* vr = reinterpret_cast<const float4*>(Vs + j * D_DIM);
                    float4 v0 = vr[0], v1 = vr[1], v2 = vr[2], v3 = vr[3];
                    accA[0]  = fmaf(pA, v0.x, accA[0]);  accA[1]  = fmaf(pA, v0.y, accA[1]);
                    accA[2]  = fmaf(pA, v0.z, accA[2]);  accA[3]  = fmaf(pA, v0.w, accA[3]);
                    accA[4]  = fmaf(pA, v1.x, accA[4]);  accA[5]  = fmaf(pA, v1.y, accA[5]);
                    accA[6]  = fmaf(pA, v1.z, accA[6]);  accA[7]  = fmaf(pA, v1.w, accA[7]);
                    accA[8]  = fmaf(pA, v2.x, accA[8]);  accA[9]  = fmaf(pA, v2.y, accA[9]);
                    accA[10] = fmaf(pA, v2.z, accA[10]); accA[11] = fmaf(pA, v2.w, accA[11]);
                    accA[12] = fmaf(pA, v3.x, accA[12]); accA[13] = fmaf(pA, v3.y, accA[13]);
                    accA[14] = fmaf(pA, v3.z, accA[14]); accA[15] = fmaf(pA, v3.w, accA[15]);
                    accB[0]  = fmaf(pB, v0.x, accB[0]);  accB[1]  = fmaf(pB, v0.y, accB[1]);
                    accB[2]  = fmaf(pB, v0.z, accB[2]);  accB[3]  = fmaf(pB, v0.w, accB[3]);
                    accB[4]  = fmaf(pB, v1.x, accB[4]);  accB[5]  = fmaf(pB, v1.y, accB[5]);
                    accB[6]  = fmaf(pB, v1.z, accB[6]);  accB[7]  = fmaf(pB, v1.w, accB[7]);
                    accB[8]  = fmaf(pB, v2.x, accB[8]);  accB[9]  = fmaf(pB, v2.y, accB[9]);
                    accB[10] = fmaf(pB, v2.z, accB[10]); accB[11] = fmaf(pB, v2.w, accB[11]);
                    accB[12] = fmaf(pB, v3.x, accB[12]); accB[13] = fmaf(pB, v3.y, accB[13]);
                    accB[14] = fmaf(pB, v3.z, accB[14]); accB[15] = fmaf(pB, v3.w, accB[15]);
                }
            }
        }
    }

    // Write partials (unnormalized).
    const int qiA = bh * S_LEN + qA;
    const int qiB = bh * S_LEN + qB;
    g_psum[(size_t)split * NQ + qiA] = sumA;
    g_psum[(size_t)split * NQ + qiB] = sumB;
    float4* paccA = reinterpret_cast<float4*>(g_pacc + ((size_t)split * NQ + qiA) * D_DIM);
    float4* paccB = reinterpret_cast<float4*>(g_pacc + ((size_t)split * NQ + qiB) * D_DIM);
#pragma unroll
    for (int i = 0; i < 4; i++) {
        paccA[i] = make_float4(accA[4*i], accA[4*i+1], accA[4*i+2], accA[4*i+3]);
        paccB[i] = make_float4(accB[4*i], accB[4*i+1], accB[4*i+2], accB[4*i+3]);
    }
}

__global__ __launch_bounds__(256)
void attn_reduce_kernel(float* __restrict__ O)
{
    const int q = blockIdx.x * 256 + threadIdx.x;   // 0..NQ-1
    float sum = 0.0f;
    float4 a0 = make_float4(0,0,0,0), a1 = a0, a2 = a0, a3 = a0;
#pragma unroll
    for (int s = 0; s < SPLIT; s++) {
        sum += g_psum[(size_t)s * NQ + q];
        const float4* p = reinterpret_cast<const float4*>(g_pacc + ((size_t)s * NQ + q) * D_DIM);
        float4 t0 = p[0], t1 = p[1], t2 = p[2], t3 = p[3];
        a0.x += t0.x; a0.y += t0.y; a0.z += t0.z; a0.w += t0.w;
        a1.x += t1.x; a1.y += t1.y; a1.z += t1.z; a1.w += t1.w;
        a2.x += t2.x; a2.y += t2.y; a2.z += t2.z; a2.w += t2.w;
        a3.x += t3.x; a3.y += t3.y; a3.z += t3.z; a3.w += t3.w;
    }
    float inv = 1.0f / sum;
    float4* op = reinterpret_cast<float4*>(O + (size_t)q * D_DIM);
    op[0] = make_float4(a0.x*inv, a0.y*inv, a0.z*inv, a0.w*inv);
    op[1] = make_float4(a1.x*inv, a1.y*inv, a1.z*inv, a1.w*inv);
    op[2] = make_float4(a2.x*inv, a2.y*inv, a2.z*inv, a2.w*inv);
    op[3] = make_float4(a3.x*inv, a3.y*inv, a3.z*inv, a3.w*inv);
}

extern "C" void kernel_launch(void* const* d_in, const int* in_sizes, int n_in,
                              void* d_out, int out_size)
{
    const float* Q = (const float*)d_in[0];
    const float* K = (const float*)d_in[1];
    const float* V = (const float*)d_in[2];
    const int* mask = (const int*)d_in[3];
    float* O = (float*)d_out;

    dim3 grid(S_LEN / QPB, B_NUM * H_NUM, SPLIT);   // (8, 32, 8) = 2048 blocks
    attn_partial_kernel<<<grid, QT>>>(Q, K, V, mask, O);
    attn_reduce_kernel<<<NQ / 256, 256>>>(O);
}

// round 5
// speedup vs baseline: 2.1108x; 1.1148x over previous
#include <cuda_runtime.h>

// DotProductAttention: B=4, H=8, S=2048, D=16, fp32.
// logits = 10*tanh(QK^T*SCALE); mask(b,key)==1 -> -1e10; softmax; O = P@V.
//
// R5 = R4 resubmit (R4 bench was an infra failure, no data).
//  - Pre-pass compacts unmasked key indices per batch (deterministic ballot/popc).
//  - Main kernel: dense, branch-free inner loop over compacted keys only.
//    Tiles gathered K/V -> smem via index list.
//  - Fixed softmax max = 10 => p = exp2(C2/(exp2(C1*q.k)+1)); exactly associative
//    => split-K x8 + deterministic reduce.
//  - 2 queries per thread amortize smem broadcast reads.

#define S_LEN   2048
#define D_DIM   16
#define H_NUM   8
#define B_NUM   4
#define NQ      65536          // B*H*S
#define QT      128            // threads per block
#define QPB     256            // queries per block (2/thread)
#define KT      128            // key tile
#define SPLIT   8

// C1 = 2*SCALE*log2(e),  C2 = -2*CLIP*log2(e)
#define C1_F  1.1047800f
#define C2_F  (-28.85390082f)

__device__ float g_pacc[(size_t)SPLIT * NQ * D_DIM];  // 33.5 MB
__device__ float g_psum[(size_t)SPLIT * NQ];          //  2.0 MB
__device__ int   g_kidx[B_NUM][S_LEN];
__device__ int   g_kcnt[B_NUM];

__device__ __forceinline__ float ex2f(float x) {
    float r; asm("ex2.approx.ftz.f32 %0, %1;" : "=f"(r) : "f"(x)); return r;
}
__device__ __forceinline__ float rcpf(float x) {
    float r; asm("rcp.approx.ftz.f32 %0, %1;" : "=f"(r) : "f"(x)); return r;
}

// ---- Pre-pass: per-batch compacted list of unmasked keys (1 warp per b). ----
__global__ void compact_kernel(const int* __restrict__ mask)
{
    const int b    = blockIdx.x;
    const int lane = threadIdx.x;            // 32 threads
    const int* Mb  = mask + (size_t)b * S_LEN;
    int base = 0;
    for (int w = 0; w < S_LEN / 32; w++) {
        int key   = w * 32 + lane;
        bool keep = (Mb[key] == 0);
        unsigned bal = __ballot_sync(0xffffffffu, keep);
        if (keep) {
            int pos = base + __popc(bal & ((1u << lane) - 1u));
            g_kidx[b][pos] = key;
        }
        base += __popc(bal);
    }
    if (lane == 0) g_kcnt[b] = base;
}

// ---- Dense inner body (j is a compacted slot in smem). ----
#define ATTN_BODY(j)                                                              \
{                                                                                 \
    const float4* kr = reinterpret_cast<const float4*>(Ks + (j) * D_DIM);         \
    float4 k0v = kr[0], k1v = kr[1], k2v = kr[2], k3v = kr[3];                    \
    float a0 = qa[0]*k0v.x + qa[1]*k0v.y + qa[2]*k0v.z + qa[3]*k0v.w;             \
    float a1 = qa[4]*k1v.x + qa[5]*k1v.y + qa[6]*k1v.z + qa[7]*k1v.w;             \
    float a2 = qa[8]*k2v.x + qa[9]*k2v.y + qa[10]*k2v.z + qa[11]*k2v.w;           \
    float a3 = qa[12]*k3v.x + qa[13]*k3v.y + qa[14]*k3v.z + qa[15]*k3v.w;         \
    float b0 = qb[0]*k0v.x + qb[1]*k0v.y + qb[2]*k0v.z + qb[3]*k0v.w;             \
    float b1 = qb[4]*k1v.x + qb[5]*k1v.y + qb[6]*k1v.z + qb[7]*k1v.w;             \
    float b2 = qb[8]*k2v.x + qb[9]*k2v.y + qb[10]*k2v.z + qb[11]*k2v.w;           \
    float b3 = qb[12]*k3v.x + qb[13]*k3v.y + qb[14]*k3v.z + qb[15]*k3v.w;         \
    float dA = (a0 + a1) + (a2 + a3);                                             \
    float dB = (b0 + b1) + (b2 + b3);                                             \
    float uA = ex2f(dA), uB = ex2f(dB);                                           \
    float pA = ex2f(C2_F * rcpf(uA + 1.0f));                                      \
    float pB = ex2f(C2_F * rcpf(uB + 1.0f));                                      \
    sumA += pA; sumB += pB;                                                       \
    const float4* vr = reinterpret_cast<const float4*>(Vs + (j) * D_DIM);         \
    float4 v0 = vr[0], v1 = vr[1], v2 = vr[2], v3 = vr[3];                        \
    accA[0]  = fmaf(pA, v0.x, accA[0]);  accA[1]  = fmaf(pA, v0.y, accA[1]);      \
    accA[2]  = fmaf(pA, v0.z, accA[2]);  accA[3]  = fmaf(pA, v0.w, accA[3]);      \
    accA[4]  = fmaf(pA, v1.x, accA[4]);  accA[5]  = fmaf(pA, v1.y, accA[5]);      \
    accA[6]  = fmaf(pA, v1.z, accA[6]);  accA[7]  = fmaf(pA, v1.w, accA[7]);      \
    accA[8]  = fmaf(pA, v2.x, accA[8]);  accA[9]  = fmaf(pA, v2.y, accA[9]);      \
    accA[10] = fmaf(pA, v2.z, accA[10]); accA[11] = fmaf(pA, v2.w, accA[11]);     \
    accA[12] = fmaf(pA, v3.x, accA[12]); accA[13] = fmaf(pA, v3.y, accA[13]);     \
    accA[14] = fmaf(pA, v3.z, accA[14]); accA[15] = fmaf(pA, v3.w, accA[15]);     \
    accB[0]  = fmaf(pB, v0.x, accB[0]);  accB[1]  = fmaf(pB, v0.y, accB[1]);      \
    accB[2]  = fmaf(pB, v0.z, accB[2]);  accB[3]  = fmaf(pB, v0.w, accB[3]);      \
    accB[4]  = fmaf(pB, v1.x, accB[4]);  accB[5]  = fmaf(pB, v1.y, accB[5]);      \
    accB[6]  = fmaf(pB, v1.z, accB[6]);  accB[7]  = fmaf(pB, v1.w, accB[7]);      \
    accB[8]  = fmaf(pB, v2.x, accB[8]);  accB[9]  = fmaf(pB, v2.y, accB[9]);      \
    accB[10] = fmaf(pB, v2.z, accB[10]); accB[11] = fmaf(pB, v2.w, accB[11]);     \
    accB[12] = fmaf(pB, v3.x, accB[12]); accB[13] = fmaf(pB, v3.y, accB[13]);     \
    accB[14] = fmaf(pB, v3.z, accB[14]); accB[15] = fmaf(pB, v3.w, accB[15]);     \
}

__global__ __launch_bounds__(QT)
void attn_partial_kernel(const float* __restrict__ Q,
                         const float* __restrict__ K,
                         const float* __restrict__ V)
{
    __shared__ float Ks[KT * D_DIM];
    __shared__ float Vs[KT * D_DIM];

    const int bh    = blockIdx.y;      // 0..31
    const int b     = bh >> 3;         // H = 8
    const int split = blockIdx.z;      // 0..7
    const int tid   = threadIdx.x;
    const int qA    = blockIdx.x * QPB + tid;
    const int qB    = qA + QT;

    const float* Kb = K + (size_t)bh * S_LEN * D_DIM;
    const float* Vb = V + (size_t)bh * S_LEN * D_DIM;

    const int cnt     = g_kcnt[b];
    const int n_tiles = (cnt + KT - 1) / KT;
    const int tps     = (n_tiles + SPLIT - 1) / SPLIT;
    const int t_beg   = split * tps;
    const int t_end   = min(t_beg + tps, n_tiles);

    // Load both queries, pre-scaled by C1 so u = exp2(dot) directly.
    float qa[D_DIM], qb[D_DIM];
    {
        const float4* pa = reinterpret_cast<const float4*>(Q + ((size_t)bh * S_LEN + qA) * D_DIM);
        const float4* pb = reinterpret_cast<const float4*>(Q + ((size_t)bh * S_LEN + qB) * D_DIM);
#pragma unroll
        for (int i = 0; i < 4; i++) {
            float4 ta = pa[i], tb = pb[i];
            qa[4*i+0] = ta.x * C1_F; qa[4*i+1] = ta.y * C1_F;
            qa[4*i+2] = ta.z * C1_F; qa[4*i+3] = ta.w * C1_F;
            qb[4*i+0] = tb.x * C1_F; qb[4*i+1] = tb.y * C1_F;
            qb[4*i+2] = tb.z * C1_F; qb[4*i+3] = tb.w * C1_F;
        }
    }

    float accA[D_DIM], accB[D_DIM];
#pragma unroll
    for (int d = 0; d < D_DIM; d++) { accA[d] = 0.0f; accB[d] = 0.0f; }
    float sumA = 0.0f, sumB = 0.0f;

    for (int t = t_beg; t < t_end; t++) {
        const int base = t * KT;
        const int nv   = min(KT, cnt - base);
        __syncthreads();
        // Gather tile: thread tid owns compacted slot tid (64B contiguous per key).
        if (tid < nv) {
            const int j = g_kidx[b][base + tid];
            const float4* kp = reinterpret_cast<const float4*>(Kb + (size_t)j * D_DIM);
            const float4* vp = reinterpret_cast<const float4*>(Vb + (size_t)j * D_DIM);
            float4* ksd = reinterpret_cast<float4*>(Ks + tid * D_DIM);
            float4* vsd = reinterpret_cast<float4*>(Vs + tid * D_DIM);
#pragma unroll
            for (int i = 0; i < 4; i++) { ksd[i] = kp[i]; vsd[i] = vp[i]; }
        }
        __syncthreads();

        if (nv == KT) {
#pragma unroll 4
            for (int j = 0; j < KT; j++) ATTN_BODY(j);
        } else {
            for (int j = 0; j < nv; j++) ATTN_BODY(j);
        }
    }

    // Write partials (unnormalized).
    const int qiA = bh * S_LEN + qA;
    const int qiB = bh * S_LEN + qB;
    g_psum[(size_t)split * NQ + qiA] = sumA;
    g_psum[(size_t)split * NQ + qiB] = sumB;
    float4* paccA = reinterpret_cast<float4*>(g_pacc + ((size_t)split * NQ + qiA) * D_DIM);
    float4* paccB = reinterpret_cast<float4*>(g_pacc + ((size_t)split * NQ + qiB) * D_DIM);
#pragma unroll
    for (int i = 0; i < 4; i++) {
        paccA[i] = make_float4(accA[4*i], accA[4*i+1], accA[4*i+2], accA[4*i+3]);
        paccB[i] = make_float4(accB[4*i], accB[4*i+1], accB[4*i+2], accB[4*i+3]);
    }
}

__global__ __launch_bounds__(256)
void attn_reduce_kernel(float* __restrict__ O)
{
    const int q = blockIdx.x * 256 + threadIdx.x;   // 0..NQ-1
    float sum = 0.0f;
    float4 a0 = make_float4(0,0,0,0), a1 = a0, a2 = a0, a3 = a0;
#pragma unroll
    for (int s = 0; s < SPLIT; s++) {
        sum += g_psum[(size_t)s * NQ + q];
        const float4* p = reinterpret_cast<const float4*>(g_pacc + ((size_t)s * NQ + q) * D_DIM);
        float4 t0 = p[0], t1 = p[1], t2 = p[2], t3 = p[3];
        a0.x += t0.x; a0.y += t0.y; a0.z += t0.z; a0.w += t0.w;
        a1.x += t1.x; a1.y += t1.y; a1.z += t1.z; a1.w += t1.w;
        a2.x += t2.x; a2.y += t2.y; a2.z += t2.z; a2.w += t2.w;
        a3.x += t3.x; a3.y += t3.y; a3.z += t3.z; a3.w += t3.w;
    }
    float inv = 1.0f / sum;
    float4* op = reinterpret_cast<float4*>(O + (size_t)q * D_DIM);
    op[0] = make_float4(a0.x*inv, a0.y*inv, a0.z*inv, a0.w*inv);
    op[1] = make_float4(a1.x*inv, a1.y*inv, a1.z*inv, a1.w*inv);
    op[2] = make_float4(a2.x*inv, a2.y*inv, a2.z*inv, a2.w*inv);
    op[3] = make_float4(a3.x*inv, a3.y*inv, a3.z*inv, a3.w*inv);
}

extern "C" void kernel_launch(void* const* d_in, const int* in_sizes, int n_in,
                              void* d_out, int out_size)
{
    const float* Q = (const float*)d_in[0];
    const float* K = (const float*)d_in[1];
    const float* V = (const float*)d_in[2];
    const int* mask = (const int*)d_in[3];
    float* O = (float*)d_out;

    compact_kernel<<<B_NUM, 32>>>(mask);
    dim3 grid(S_LEN / QPB, B_NUM * H_NUM, SPLIT);   // (8, 32, 8)
    attn_partial_kernel<<<grid, QT>>>(Q, K, V);
    attn_reduce_kernel<<<NQ / 256, 256>>>(O);
}